// round 10
// baseline (speedup 1.0000x reference)
#include <cuda_runtime.h>
#include <cuda_bf16.h>
#include <cstdint>

#define B 4
#define L 512
#define D 128
#define QT 16            // queries per block
#define EPSV 1e-8f

typedef unsigned long long ull;

// Virtual-row slots in XsT (pair-packed for f32x2):
//   0..15  : q rows   (global q0+r    @ Wt)
//   16..31 : k rows   (tile rows 1..16 @ Wx)
//   32     : k halo   (tile row 0 = X[q0-1]  @ Wx)
//   33     : k halo   (tile row 17 = X[q0+16] @ Wx)
#define OFF_WTS 0              // [128][128]
#define OFF_WXS 16384          // [128][128]
#define OFF_XST 32768          // [128][36]
#define OFF_XS  37376          // [18][128] row-major X tile (rows q0-1..q0+16)
#define OFF_QKS 39680          // [18][128] k rows (tile rows 0..17)
#define OFF_QQS 41984          // [16][128] q rows
#define SMEM_FLOATS 44032
#define SMEM_BYTES (SMEM_FLOATS * 4)

__device__ __forceinline__ void cp_async16(void* dst, const void* src) {
    unsigned int s = (unsigned int)__cvta_generic_to_shared(dst);
    asm volatile("cp.async.ca.shared.global [%0], [%1], 16;" :: "r"(s), "l"(src));
}
__device__ __forceinline__ void cp_commit() {
    asm volatile("cp.async.commit_group;");
}
template<int N>
__device__ __forceinline__ void cp_wait() {
    asm volatile("cp.async.wait_group %0;" :: "n"(N));
}

__device__ __forceinline__ ull ffma2(ull a, ull b, ull c) {
    ull d;
    asm("fma.rn.f32x2 %0, %1, %2, %3;" : "=l"(d) : "l"(a), "l"(b), "l"(c));
    return d;
}
__device__ __forceinline__ ull dup2(float x) {
    ull d;
    unsigned int u = __float_as_uint(x);
    asm("mov.b64 %0, {%1, %1};" : "=l"(d) : "r"(u));
    return d;
}

// accurate tanh: 1 - 2/(e^{2x}+1)
__device__ __forceinline__ float tanh_acc(float x) {
    float e2 = __expf(2.0f * x);
    return 1.0f - __fdividef(2.0f, e2 + 1.0f);
}

// ---------------------------------------------------------------------------
// grid: (L/QT, B) = (32, 4) = 128 blocks; 1024 threads (32 warps).
// GEMM: 8 rowgroups x 4 colgroups. Groups 0-6: 4 row-slots; group 7: 6 slots.
// ---------------------------------------------------------------------------
__global__ __launch_bounds__(1024, 1) void fused_kernel(
    const float* __restrict__ X,  const float* __restrict__ Wt,
    const float* __restrict__ Wx, const float* __restrict__ Wa,
    const float* __restrict__ bh, const float* __restrict__ ba_p,
    float* __restrict__ out)
{
    extern __shared__ float sm[];
    float* Wts = sm + OFF_WTS;
    float* Wxs = sm + OFF_WXS;
    float* XsT = sm + OFF_XST;   // [d][36]
    float* Xs  = sm + OFF_XS;
    float* qks = sm + OFF_QKS;
    float* qqs = sm + OFF_QQS;

    const int b    = blockIdx.y;
    const int q0   = blockIdx.x * QT;
    const int tid  = threadIdx.x;
    const int wid  = tid >> 5;
    const int lane = tid & 31;
    const int g    = wid >> 2;     // rowgroup 0..7
    const int cgrp = wid & 3;      // colgroup 0..3
    const float* XB = X + b * L * D;

    // ---- stage weights: group0 = d<64 of both, group1 = d>=64 ----
    {
        const float4* Wt4 = (const float4*)Wt;
        const float4* Wx4 = (const float4*)Wx;
        #pragma unroll
        for (int j = 0; j < 2; j++) {
            int idx = j * 1024 + tid;              // d < 64
            cp_async16(Wts + idx * 4, Wt4 + idx);
            cp_async16(Wxs + idx * 4, Wx4 + idx);
        }
        cp_commit();
        #pragma unroll
        for (int j = 2; j < 4; j++) {
            int idx = j * 1024 + tid;              // d >= 64
            cp_async16(Wts + idx * 4, Wt4 + idx);
            cp_async16(Wxs + idx * 4, Wx4 + idx);
        }
        cp_commit();
    }

    // ---- X tile: 18 rows (q0-1 .. q0+16 clamped); row-major + slotted ----
    if (tid < 18 * 32) {
        int r  = tid >> 5;         // tile row 0..17
        int d4 = tid & 31;
        int row = min(max(q0 - 1 + r, 0), L - 1);
        float4 v = ((const float4*)(XB + row * D))[d4];
        ((float4*)(Xs + r * D))[d4] = v;
        int d0 = d4 * 4;
        int ks = (r == 0) ? 32 : (r == 17) ? 33 : (15 + r);   // k slot
        XsT[(d0 + 0) * 36 + ks] = v.x;
        XsT[(d0 + 1) * 36 + ks] = v.y;
        XsT[(d0 + 2) * 36 + ks] = v.z;
        XsT[(d0 + 3) * 36 + ks] = v.w;
        if (r >= 1 && r <= 16) {                               // q slot
            int qsl = r - 1;
            XsT[(d0 + 0) * 36 + qsl] = v.x;
            XsT[(d0 + 1) * 36 + qsl] = v.y;
            XsT[(d0 + 2) * 36 + qsl] = v.z;
            XsT[(d0 + 3) * 36 + qsl] = v.w;
        }
    }

    // ---- GEMM ----
    const int col = cgrp * 32 + lane;
    const float* Wp = ((g < 4) ? Wts : Wxs) + col;
    const float* xp = XsT + ((g < 7) ? g * 4 : 28);

    ull acc[3] = {0, 0, 0};

    cp_wait<1>();
    __syncthreads();

    if (g < 7) {
        #pragma unroll 8
        for (int d = 0; d < 64; d++) {
            ull wd = dup2(Wp[d * D]);
            ulonglong2 xa = *(const ulonglong2*)(xp + d * 36);
            acc[0] = ffma2(xa.x, wd, acc[0]);
            acc[1] = ffma2(xa.y, wd, acc[1]);
        }
    } else {
        #pragma unroll 8
        for (int d = 0; d < 64; d++) {
            ull wd = dup2(Wp[d * D]);
            ulonglong2 xa = *(const ulonglong2*)(xp + d * 36);
            ull xc = *(const ull*)(xp + d * 36 + 4);
            acc[0] = ffma2(xa.x, wd, acc[0]);
            acc[1] = ffma2(xa.y, wd, acc[1]);
            acc[2] = ffma2(xc,   wd, acc[2]);
        }
    }

    cp_wait<0>();
    __syncthreads();

    if (g < 7) {
        #pragma unroll 8
        for (int d = 64; d < 128; d++) {
            ull wd = dup2(Wp[d * D]);
            ulonglong2 xa = *(const ulonglong2*)(xp + d * 36);
            acc[0] = ffma2(xa.x, wd, acc[0]);
            acc[1] = ffma2(xa.y, wd, acc[1]);
        }
    } else {
        #pragma unroll 8
        for (int d = 64; d < 128; d++) {
            ull wd = dup2(Wp[d * D]);
            ulonglong2 xa = *(const ulonglong2*)(xp + d * 36);
            ull xc = *(const ull*)(xp + d * 36 + 4);
            acc[0] = ffma2(xa.x, wd, acc[0]);
            acc[1] = ffma2(xa.y, wd, acc[1]);
            acc[2] = ffma2(xc,   wd, acc[2]);
        }
    }

    // ---- store unit results (slot -> qqs/qks) ----
    {
        const int s0 = (g < 7) ? g * 4 : 28;
        const int nacc = (g < 7) ? 2 : 3;
        #pragma unroll
        for (int j = 0; j < 3; j++) {
            if (j >= nacc) break;
            float2 f = *(float2*)&acc[j];
            #pragma unroll
            for (int h = 0; h < 2; h++) {
                int slot = s0 + 2 * j + h;
                float v = h ? f.y : f.x;
                if (slot < 16)       qqs[slot * D + col] = v;
                else if (slot < 32)  qks[(slot - 15) * D + col] = v;
                else if (slot == 32) qks[0 * D + col]  = v;
                else                 qks[17 * D + col] = v;
            }
        }
    }
    __syncthreads();

    // ---- window phase: warps 0..15, warp == query ----
    if (wid < 16) {
        const int rq = wid;
        const int qi = q0 + rq;

        float4 qv  = ((const float4*)(qqs + rq * D))[lane];
        float4 bhv = ((const float4*)bh)[lane];
        qv.x += bhv.x; qv.y += bhv.y; qv.z += bhv.z; qv.w += bhv.w;
        const float4 wv = ((const float4*)Wa)[lane];
        const float bav = ba_p[0];

        float e[3];
        #pragma unroll
        for (int tt = 0; tt < 3; tt++) {
            int j = qi - 1 + tt;                   // global key, tile row rq+tt
            float4 kv = ((const float4*)(qks + (rq + tt) * D))[lane];
            float p = tanh_acc(qv.x + kv.x) * wv.x
                    + tanh_acc(qv.y + kv.y) * wv.y
                    + tanh_acc(qv.z + kv.z) * wv.z
                    + tanh_acc(qv.w + kv.w) * wv.w;
            #pragma unroll
            for (int o = 16; o > 0; o >>= 1)
                p += __shfl_xor_sync(0xffffffffu, p, o);
            e[tt] = (j >= 0 && j < L) ? (p + bav) : -1e30f;
        }

        float m  = fmaxf(e[0], fmaxf(e[1], e[2]));
        float w0 = __expf(e[0] - m);
        float w1 = __expf(e[1] - m);
        float w2 = __expf(e[2] - m);
        float inv = __fdividef(1.0f, w0 + w1 + w2 + EPSV);

        float4 o4 = make_float4(0.f, 0.f, 0.f, 0.f);
        #pragma unroll
        for (int tt = 0; tt < 3; tt++) {
            float w = (tt == 0) ? w0 : (tt == 1) ? w1 : w2;
            float a = w * inv;
            float4 xv = ((const float4*)(Xs + (rq + tt) * D))[lane];
            o4.x = fmaf(a, xv.x, o4.x);
            o4.y = fmaf(a, xv.y, o4.y);
            o4.z = fmaf(a, xv.z, o4.z);
            o4.w = fmaf(a, xv.w, o4.w);
        }
        ((float4*)(out + (b * L + qi) * D))[lane] = o4;
    }
}

extern "C" void kernel_launch(void* const* d_in, const int* in_sizes, int n_in,
                              void* d_out, int out_size)
{
    const float* X  = (const float*)d_in[0];
    const float* Wt = (const float*)d_in[1];
    const float* Wx = (const float*)d_in[2];
    const float* Wa = (const float*)d_in[3];
    const float* bh = (const float*)d_in[4];
    const float* ba = (const float*)d_in[5];
    float* out = (float*)d_out;

    cudaFuncSetAttribute(fused_kernel,
                         cudaFuncAttributeMaxDynamicSharedMemorySize, SMEM_BYTES);
    dim3 grid(L / QT, B);
    fused_kernel<<<grid, 1024, SMEM_BYTES>>>(X, Wt, Wx, Wa, bh, ba, out);
}

// round 12
// speedup vs baseline: 1.4448x; 1.4448x over previous
#include <cuda_runtime.h>
#include <cuda_bf16.h>
#include <cstdint>

#define B 4
#define L 512
#define D 128
#define QT 16            // queries per block
#define NTOT 256         // output cols: 0..127 = Wt, 128..255 = Wx
#define EPSV 1e-8f

// precomputed n-major bf16 weights: [n][d], n<128 -> Wt col n, else Wx col n-128
__device__ __align__(16) __nv_bfloat16 g_Whi[NTOT * D];
__device__ __align__(16) __nv_bfloat16 g_Wlo[NTOT * D];

// ---- smem carve (byte offsets) ----
#define OFF_BHI 0                 // [256 n][16 chunks of 16B]  (swizzled)
#define OFF_BLO 65536
#define OFF_AHI 131072            // [32 r][16 chunks]          (swizzled)
#define OFF_ALO 139264
#define OFF_XS  147456            // fp32 [18][128]
#define OFF_C   156672            // fp32 [32][260]
#define SMEM_BYTES 189952
#define CSTRIDE 260

__device__ __forceinline__ unsigned smem_u32(const void* p) {
    return (unsigned)__cvta_generic_to_shared(p);
}
__device__ __forceinline__ void cp_async16(void* dst, const void* src) {
    asm volatile("cp.async.ca.shared.global [%0], [%1], 16;"
                 :: "r"(smem_u32(dst)), "l"(src));
}
__device__ __forceinline__ void cp_commit() {
    asm volatile("cp.async.commit_group;");
}
__device__ __forceinline__ void cp_wait0() {
    asm volatile("cp.async.wait_group 0;");
}

__device__ __forceinline__ void ldsm_x4(unsigned* r, unsigned addr) {
    asm volatile("ldmatrix.sync.aligned.m8n8.x4.shared.b16 {%0,%1,%2,%3}, [%4];"
                 : "=r"(r[0]), "=r"(r[1]), "=r"(r[2]), "=r"(r[3]) : "r"(addr));
}
__device__ __forceinline__ void ldsm_x2(unsigned& r0, unsigned& r1, unsigned addr) {
    asm volatile("ldmatrix.sync.aligned.m8n8.x2.shared.b16 {%0,%1}, [%2];"
                 : "=r"(r0), "=r"(r1) : "r"(addr));
}
__device__ __forceinline__ void mma_bf16(float* c, const unsigned* a,
                                         unsigned b0, unsigned b1) {
    asm volatile(
        "mma.sync.aligned.m16n8k16.row.col.f32.bf16.bf16.f32 "
        "{%0,%1,%2,%3}, {%4,%5,%6,%7}, {%8,%9}, {%0,%1,%2,%3};"
        : "+f"(c[0]), "+f"(c[1]), "+f"(c[2]), "+f"(c[3])
        : "r"(a[0]), "r"(a[1]), "r"(a[2]), "r"(a[3]), "r"(b0), "r"(b1));
}

// accurate tanh: 1 - 2/(e^{2x}+1)
__device__ __forceinline__ float tanh_acc(float x) {
    float e2 = __expf(2.0f * x);
    return 1.0f - __fdividef(2.0f, e2 + 1.0f);
}

// ---------------------------------------------------------------------------
// prep: Wt/Wx fp32 [d][c]  ->  g_Whi/g_Wlo bf16 [n][d]
// grid 256 blocks x 128 threads
// ---------------------------------------------------------------------------
__global__ __launch_bounds__(128) void prep_kernel(
    const float* __restrict__ Wt, const float* __restrict__ Wx)
{
    const int n = blockIdx.x;
    const int d = threadIdx.x;
    const float* W = (n < 128) ? Wt : Wx;
    float v = W[d * D + (n & 127)];
    __nv_bfloat16 hi = __float2bfloat16_rn(v);
    __nv_bfloat16 lo = __float2bfloat16_rn(v - __bfloat162float(hi));
    g_Whi[n * D + d] = hi;
    g_Wlo[n * D + d] = lo;
}

// ---------------------------------------------------------------------------
// main: grid (L/QT, B) = (32, 4) = 128 blocks; 512 threads (16 warps).
// C[32x256] = Atile(bf16 split) @ [Wt|Wx](bf16 split), HMMA 3-term.
// Tile rows 0..17 = X[q0-1 .. q0+16] (clamped). q row r = C[r+1][c],
// k tile row r = C[r][128+c]. Then window softmax + output.
// ---------------------------------------------------------------------------
__global__ __launch_bounds__(512, 1) void fused_kernel(
    const float* __restrict__ X,  const float* __restrict__ Wa,
    const float* __restrict__ bh, const float* __restrict__ ba_p,
    float* __restrict__ out)
{
    extern __shared__ char smem[];
    char* BHI = smem + OFF_BHI;
    char* BLO = smem + OFF_BLO;
    char* AHI = smem + OFF_AHI;
    char* ALO = smem + OFF_ALO;
    float* Xs = (float*)(smem + OFF_XS);
    float* Cs = (float*)(smem + OFF_C);

    const int b    = blockIdx.y;
    const int q0   = blockIdx.x * QT;
    const int tid  = threadIdx.x;
    const int wid  = tid >> 5;
    const int lane = tid & 31;
    const float* XB = X + b * L * D;

    // ---- stage B (bf16 hi/lo, n-major, swizzled) via cp.async ----
    #pragma unroll
    for (int it = 0; it < 16; it++) {
        int idx = it * 512 + tid;          // 0..8191
        int mat = idx >> 12;               // 0 = hi, 1 = lo
        int n   = (idx >> 4) & 255;
        int c   = idx & 15;
        const __nv_bfloat16* src = (mat ? g_Wlo : g_Whi) + n * D + c * 8;
        char* dst = (mat ? BLO : BHI) + n * 256 + ((c ^ (n & 7)) << 4);
        cp_async16(dst, src);
    }
    cp_commit();

    // ---- A tile: 18 rows fp32 + bf16 hi/lo (swizzled); 576 items, 512 thr ----
    for (int i = tid; i < 18 * 32; i += 512) {
        int r  = i >> 5;                   // tile row 0..17
        int d4 = i & 31;
        int row = min(max(q0 - 1 + r, 0), L - 1);
        float4 v = ((const float4*)(XB + row * D))[d4];
        ((float4*)(Xs + r * D))[d4] = v;

        unsigned short hx = __bfloat16_as_ushort(__float2bfloat16_rn(v.x));
        unsigned short hy = __bfloat16_as_ushort(__float2bfloat16_rn(v.y));
        unsigned short hz = __bfloat16_as_ushort(__float2bfloat16_rn(v.z));
        unsigned short hw = __bfloat16_as_ushort(__float2bfloat16_rn(v.w));
        float lxf = v.x - __bfloat162float(__ushort_as_bfloat16(hx));
        float lyf = v.y - __bfloat162float(__ushort_as_bfloat16(hy));
        float lzf = v.z - __bfloat162float(__ushort_as_bfloat16(hz));
        float lwf = v.w - __bfloat162float(__ushort_as_bfloat16(hw));
        unsigned short lx = __bfloat16_as_ushort(__float2bfloat16_rn(lxf));
        unsigned short ly = __bfloat16_as_ushort(__float2bfloat16_rn(lyf));
        unsigned short lz = __bfloat16_as_ushort(__float2bfloat16_rn(lzf));
        unsigned short lw = __bfloat16_as_ushort(__float2bfloat16_rn(lwf));

        int off = r * 256 + (((d4 >> 1) ^ (r & 7)) << 4) + ((d4 & 1) << 3);
        *(uint2*)(AHI + off) = make_uint2((unsigned)hx | ((unsigned)hy << 16),
                                          (unsigned)hz | ((unsigned)hw << 16));
        *(uint2*)(ALO + off) = make_uint2((unsigned)lx | ((unsigned)ly << 16),
                                          (unsigned)lz | ((unsigned)lw << 16));
    }

    cp_wait0();
    __syncthreads();

    // ---- HMMA GEMM: warp = (mtile, 32-col group) ----
    const int m0 = (wid >> 3) * 16;        // 0 or 16
    const int n0 = (wid & 7) * 32;

    float cfr[4][4];
    #pragma unroll
    for (int nt = 0; nt < 4; nt++)
        #pragma unroll
        for (int j = 0; j < 4; j++) cfr[nt][j] = 0.f;

    const int qd   = lane >> 3;            // A quadrant
    const int arow = m0 + ((qd & 1) << 3) + (lane & 7);
    const int bl   = lane & 15;
    const int bkh  = bl >> 3;              // B k-chunk half
    const int bno  = bl & 7;               // B n offset within tile

    #pragma unroll
    for (int kk = 0; kk < 8; kk++) {
        const int kc = kk * 2;             // 16B-chunk base for this k16
        unsigned ahi[4], alo[4];
        {
            int ac = (kc + (qd >> 1)) ^ (arow & 7);
            ldsm_x4(ahi, smem_u32(AHI + arow * 256 + (ac << 4)));
            ldsm_x4(alo, smem_u32(ALO + arow * 256 + (ac << 4)));
        }
        #pragma unroll
        for (int nt = 0; nt < 4; nt++) {
            int n  = n0 + nt * 8 + bno;
            int bc = (kc + bkh) ^ (n & 7);
            unsigned bh0, bh1, bl0, bl1;
            ldsm_x2(bh0, bh1, smem_u32(BHI + n * 256 + (bc << 4)));
            ldsm_x2(bl0, bl1, smem_u32(BLO + n * 256 + (bc << 4)));
            mma_bf16(cfr[nt], ahi, bh0, bh1);
            mma_bf16(cfr[nt], ahi, bl0, bl1);
            mma_bf16(cfr[nt], alo, bh0, bh1);
        }
    }

    // ---- epilogue: c-frags -> Cs[32][260] ----
    {
        int r0 = m0 + (lane >> 2);
        int r1 = r0 + 8;
        int c0 = (lane & 3) * 2;
        #pragma unroll
        for (int nt = 0; nt < 4; nt++) {
            int col = n0 + nt * 8 + c0;
            *(float2*)&Cs[r0 * CSTRIDE + col] = make_float2(cfr[nt][0], cfr[nt][1]);
            *(float2*)&Cs[r1 * CSTRIDE + col] = make_float2(cfr[nt][2], cfr[nt][3]);
        }
    }
    __syncthreads();

    // ---- window phase: 16 warps, warp == query ----
    const int rq = wid;                    // 0..15
    const int qi = q0 + rq;

    float4 qv  = *(const float4*)&Cs[(rq + 1) * CSTRIDE + lane * 4];   // q part
    float4 bhv = ((const float4*)bh)[lane];
    qv.x += bhv.x; qv.y += bhv.y; qv.z += bhv.z; qv.w += bhv.w;
    const float4 wv = ((const float4*)Wa)[lane];
    const float bav = ba_p[0];

    float e[3];
    #pragma unroll
    for (int tt = 0; tt < 3; tt++) {
        int j = qi - 1 + tt;                                // global key
        float4 kv = *(const float4*)&Cs[(rq + tt) * CSTRIDE + 128 + lane * 4];
        float p = tanh_acc(qv.x + kv.x) * wv.x
                + tanh_acc(qv.y + kv.y) * wv.y
                + tanh_acc(qv.z + kv.z) * wv.z
                + tanh_acc(qv.w + kv.w) * wv.w;
        #pragma unroll
        for (int o = 16; o > 0; o >>= 1)
            p += __shfl_xor_sync(0xffffffffu, p, o);
        e[tt] = (j >= 0 && j < L) ? (p + bav) : -1e30f;
    }

    float m  = fmaxf(e[0], fmaxf(e[1], e[2]));
    float w0 = __expf(e[0] - m);
    float w1 = __expf(e[1] - m);
    float w2 = __expf(e[2] - m);
    float inv = __fdividef(1.0f, w0 + w1 + w2 + EPSV);

    float4 o4 = make_float4(0.f, 0.f, 0.f, 0.f);
    #pragma unroll
    for (int tt = 0; tt < 3; tt++) {
        float w = (tt == 0) ? w0 : (tt == 1) ? w1 : w2;
        float a = w * inv;
        float4 xv = ((const float4*)(Xs + (rq + tt) * D))[lane];
        o4.x = fmaf(a, xv.x, o4.x);
        o4.y = fmaf(a, xv.y, o4.y);
        o4.z = fmaf(a, xv.z, o4.z);
        o4.w = fmaf(a, xv.w, o4.w);
    }
    ((float4*)(out + (b * L + qi) * D))[lane] = o4;
}

extern "C" void kernel_launch(void* const* d_in, const int* in_sizes, int n_in,
                              void* d_out, int out_size)
{
    const float* X  = (const float*)d_in[0];
    const float* Wt = (const float*)d_in[1];
    const float* Wx = (const float*)d_in[2];
    const float* Wa = (const float*)d_in[3];
    const float* bh = (const float*)d_in[4];
    const float* ba = (const float*)d_in[5];
    float* out = (float*)d_out;

    prep_kernel<<<NTOT, 128>>>(Wt, Wx);

    cudaFuncSetAttribute(fused_kernel,
                         cudaFuncAttributeMaxDynamicSharedMemorySize, SMEM_BYTES);
    dim3 grid(L / QT, B);
    fused_kernel<<<grid, 512, SMEM_BYTES>>>(X, Wa, bh, ba, out);
}